// round 8
// baseline (speedup 1.0000x reference)
#include <cuda_runtime.h>
#include <cuda_bf16.h>

// Device-global scratch (no allocations allowed).
__device__ float    g_M1[100 * 100];   // level-1 partials (row-major 10x10 each)
__device__ float    g_c1[100 * 10];
__device__ float    g_M3[100];         // final composed matrix [out][in]
__device__ float    g_c3[10];          // final composed bias
__device__ unsigned g_ctr1;            // level-1 arrivals (0..13 CTAs)
__device__ unsigned g_flag;            // fold complete
__device__ unsigned g_tile;            // dynamic tile counter
__device__ unsigned g_done;            // CTA-done counter (reset logic)

#define TPB 256
#define NSTAGE 5
#define STAGE_PAIRS 240                      // 8 warps x 30 pairs
#define STAGE_FLOATS (STAGE_PAIRS * 20)      // 4800 floats = 19200 B
#define STAGE0_F 128                         // stages start (512B offset)
#define SMEM_FLOATS (STAGE0_F + NSTAGE * STAGE_FLOATS)   // 24128
#define SMEM_BYTES (SMEM_FLOATS * 4)                     // 96512 -> 2 CTAs/SM

// ---------------------------------------------------------------------------
// PTX helpers (cp.async.bulk 1D + mbarrier).
// ---------------------------------------------------------------------------
__device__ __forceinline__ unsigned smem_u32(const void* p) {
    unsigned r;
    asm("{ .reg .u64 t; cvta.to.shared.u64 t, %1; cvt.u32.u64 %0, t; }"
        : "=r"(r) : "l"(p));
    return r;
}
__device__ __forceinline__ void mbar_init(unsigned addr, unsigned count) {
    asm volatile("mbarrier.init.shared.b64 [%0], %1;" :: "r"(addr), "r"(count) : "memory");
}
__device__ __forceinline__ void mbar_expect_tx(unsigned addr, unsigned bytes) {
    asm volatile("mbarrier.arrive.expect_tx.shared.b64 _, [%0], %1;"
                 :: "r"(addr), "r"(bytes) : "memory");
}
__device__ __forceinline__ void bulk_load(unsigned dst_smem, const void* src_gmem,
                                          unsigned bytes, unsigned mbar) {
    asm volatile("cp.async.bulk.shared::cta.global.mbarrier::complete_tx::bytes "
                 "[%0], [%1], %2, [%3];"
                 :: "r"(dst_smem), "l"(src_gmem), "r"(bytes), "r"(mbar) : "memory");
}
__device__ __forceinline__ void mbar_wait(unsigned addr, unsigned parity) {
    unsigned done;
    asm volatile("{\n\t.reg .pred p;\n\t"
                 "mbarrier.try_wait.parity.acquire.cta.shared::cta.b64 p, [%1], %2;\n\t"
                 "selp.b32 %0, 1, 0, p;\n\t}"
                 : "=r"(done) : "r"(addr), "r"(parity) : "memory");
    while (!done) {
        asm volatile("{\n\t.reg .pred p;\n\t"
                     "mbarrier.try_wait.parity.acquire.cta.shared::cta.b64 p, [%1], %2, 0x989680;\n\t"
                     "selp.b32 %0, 1, 0, p;\n\t}"
                     : "=r"(done) : "r"(addr), "r"(parity) : "memory");
    }
}

// ---------------------------------------------------------------------------
// Warp-level fold of a chain of n affine maps stored in smem:
//   Wsm: n matrices (row-major [i][k], 100 floats each), bsm: n biases (10 each).
// Lane j<10 ends holding column j of the composite M (m[k] = M[k][j]);
// lane 10 ends holding the composite bias (m[k] = c[k]).
// No warp divergence in the hot loop; no block barriers.
// ---------------------------------------------------------------------------
__device__ __forceinline__ void warp_fold_chain(const float* __restrict__ Wsm,
                                                const float* __restrict__ bsm,
                                                int n, int lane, float m[10]) {
    #pragma unroll
    for (int k = 0; k < 10; ++k)
        m[k] = (lane < 10) ? Wsm[k * 10 + lane] : bsm[k];

    #pragma unroll 1
    for (int s = 1; s < n; ++s) {
        const float2* Wr = (const float2*)(Wsm + s * 100);
        float acc[10];
        #pragma unroll
        for (int i = 0; i < 10; ++i) {
            const float2 w0 = Wr[i * 5 + 0];
            const float2 w1 = Wr[i * 5 + 1];
            const float2 w2 = Wr[i * 5 + 2];
            const float2 w3 = Wr[i * 5 + 3];
            const float2 w4 = Wr[i * 5 + 4];
            float a;
            a = w0.x * m[0];
            a = fmaf(w0.y, m[1], a);
            a = fmaf(w1.x, m[2], a);
            a = fmaf(w1.y, m[3], a);
            a = fmaf(w2.x, m[4], a);
            a = fmaf(w2.y, m[5], a);
            a = fmaf(w3.x, m[6], a);
            a = fmaf(w3.y, m[7], a);
            a = fmaf(w4.x, m[8], a);
            a = fmaf(w4.y, m[9], a);
            acc[i] = a;
        }
        if (lane == 10) {
            #pragma unroll
            for (int i = 0; i < 10; ++i) acc[i] += bsm[s * 10 + i];
        }
        #pragma unroll
        for (int i = 0; i < 10; ++i) m[i] = acc[i];
    }
}

__device__ __forceinline__ void warp_copy4(float* dst, const float* src,
                                           int nfloats, int lane) {
    const float4* s4 = (const float4*)src;
    float4* d4 = (float4*)dst;
    for (int i = lane; i < nfloats / 4; i += 32) d4[i] = s4[i];
}
__device__ __forceinline__ void warp_copy1(float* dst, const float* src,
                                           int nfloats, int lane) {
    for (int i = lane; i < nfloats; i += 32) dst[i] = src[i];
}

// ---------------------------------------------------------------------------
// issue one tile's bulk load into stage s.
// ---------------------------------------------------------------------------
__device__ __forceinline__ void issue_tile(float* SH, unsigned bar_s, int s,
                                           long long tile, long long pairs,
                                           const float* x) {
    const long long pbase = tile * STAGE_PAIRS;
    const long long rem = pairs - pbase;
    const unsigned np = (unsigned)(rem < STAGE_PAIRS ? rem : STAGE_PAIRS);
    mbar_expect_tx(bar_s, np * 80u);
    bulk_load(smem_u32(&SH[STAGE0_F + s * STAGE_FLOATS]), x + pbase * 20, np * 80u, bar_s);
}

// ---------------------------------------------------------------------------
// ONE fused persistent kernel (grid = 296 = 2 CTAs/SM, 96.5KB smem each):
//  - CTAs >= 14: TMA prologue immediately (prefill hides the fold).
//  - CTAs 0..12: 8 warps fold one 10-layer chunk each (warp-level, no barriers)
//    -> g_M1/g_c1; then prologue.
//  - CTA 13: polls, 8 warps fold 12-13 partials each, warp 0 folds the final 8
//    -> g_M3/g_c3, sets g_flag; then prologue.
//  - All CTAs: wait flag, then dynamic-stolen TMA-pipelined apply.
// ---------------------------------------------------------------------------
__global__ void __launch_bounds__(TPB, 2) fused_kernel(const float* __restrict__ Ws,
                                                       const float* __restrict__ bs,
                                                       const float* __restrict__ x,
                                                       float* __restrict__ out,
                                                       long long pairs,
                                                       long long rows) {
    extern __shared__ float SH[];
    const int tid  = threadIdx.x;
    const int cta  = blockIdx.x;
    const int lane = tid & 31;
    const int warp = tid >> 5;

    // mbarriers: SH[0..9]; tile ids: SH[32..41] (as long long[5]).
    unsigned bar[NSTAGE];
    #pragma unroll
    for (int s = 0; s < NSTAGE; ++s) bar[s] = smem_u32(&SH[s * 2]);
    long long* tidsm = (long long*)&SH[32];

    if (tid == 0) {
        #pragma unroll
        for (int s = 0; s < NSTAGE; ++s) mbar_init(bar[s], 1);
    }
    __syncthreads();

    const long long tiles = (pairs + STAGE_PAIRS - 1) / STAGE_PAIRS;

    // ================= FOLD (CTAs 0..13) / PROLOGUE (others) =================
    if (cta >= 14) {
        if (tid == 0) {
            #pragma unroll
            for (int s = 0; s < NSTAGE; ++s) {
                const long long t = (long long)atomicAdd(&g_tile, 1u);
                if (t < tiles) { tidsm[s] = t; issue_tile(SH, bar[s], s, t, pairs, x); }
                else           { tidsm[s] = -1; }
            }
        }
    } else if (cta < 13) {
        // ---- Level 1: warp -> chunk = cta*8 + warp (layers [10c,10c+10)) ----
        const int chunk = cta * 8 + warp;
        float* slot = SH + STAGE0_F + warp * 1104;    // 1000 W + 100 b
        if (chunk < 100) {
            warp_copy4(slot,        Ws + (size_t)chunk * 1000, 1000, lane);
            warp_copy4(slot + 1000, bs + (size_t)chunk * 100,  100,  lane);
            __syncwarp();
            float m[10];
            warp_fold_chain(slot, slot + 1000, 10, lane, m);
            if (lane < 10) {
                #pragma unroll
                for (int k = 0; k < 10; ++k) g_M1[chunk * 100 + k * 10 + lane] = m[k];
            } else if (lane == 10) {
                #pragma unroll
                for (int k = 0; k < 10; ++k) g_c1[chunk * 10 + k] = m[k];
            }
        }
        __threadfence();
        __syncthreads();
        if (tid == 0) {
            atomicAdd(&g_ctr1, 1u);
            // prologue after fold (stage smem was fold scratch)
            #pragma unroll
            for (int s = 0; s < NSTAGE; ++s) {
                const long long t = (long long)atomicAdd(&g_tile, 1u);
                if (t < tiles) { tidsm[s] = t; issue_tile(SH, bar[s], s, t, pairs, x); }
                else           { tidsm[s] = -1; }
            }
        }
    } else { // cta == 13: levels 2 & 3
        if (tid == 0) {
            while (*(volatile unsigned*)&g_ctr1 < 13u) __nanosleep(32);
        }
        __syncthreads();
        __threadfence();   // acquire

        // ---- Level 2: warp w folds partial chunks [start, start+len) ----
        const int len   = (warp < 4) ? 13 : 12;
        const int start = (warp < 4) ? warp * 13 : 52 + (warp - 4) * 12;
        float* slot = SH + STAGE0_F + warp * 1440;        // 1300 W + 130 b
        float* W3   = SH + STAGE0_F + 8 * 1440;           // 800
        float* b3   = W3 + 800;                           // 80

        warp_copy4(slot,        g_M1 + start * 100, len * 100, lane);
        warp_copy1(slot + 1300, g_c1 + start * 10,  len * 10,  lane);
        __syncwarp();
        float m[10];
        warp_fold_chain(slot, slot + 1300, len, lane, m);
        if (lane < 10) {
            #pragma unroll
            for (int k = 0; k < 10; ++k) W3[warp * 100 + k * 10 + lane] = m[k];
        } else if (lane == 10) {
            #pragma unroll
            for (int k = 0; k < 10; ++k) b3[warp * 10 + k] = m[k];
        }
        __syncthreads();

        // ---- Level 3: warp 0 folds the 8 warp-partials ----
        if (warp == 0) {
            float mm[10];
            warp_fold_chain(W3, b3, 8, lane, mm);
            if (lane < 10) {
                #pragma unroll
                for (int k = 0; k < 10; ++k) g_M3[k * 10 + lane] = mm[k];
            } else if (lane == 10) {
                #pragma unroll
                for (int k = 0; k < 10; ++k) g_c3[k] = mm[k];
            }
        }
        __threadfence();
        __syncthreads();
        if (tid == 0) {
            *(volatile unsigned*)&g_flag = 1u;   // release (fence above)
            #pragma unroll
            for (int s = 0; s < NSTAGE; ++s) {
                const long long t = (long long)atomicAdd(&g_tile, 1u);
                if (t < tiles) { tidsm[s] = t; issue_tile(SH, bar[s], s, t, pairs, x); }
                else           { tidsm[s] = -1; }
            }
        }
    }

    // ================= WAIT FOR THE COMPOSED AFFINE =================
    if (tid == 0) {
        while (*(volatile unsigned*)&g_flag == 0u) __nanosleep(32);
    }
    __syncthreads();
    __threadfence();   // acquire

    // Per-lane constants. phase = lane%5 decides which 4 output floats.
    const int phase = lane % 5;
    const int lp    = lane / 5;              // 5-lane group (0..5; 6 -> inactive)
    const bool active = (lane < 30);
    const int offA = (phase >= 3) ? 10 : 0;  // source row for outputs w=0,1
    const int offB = (phase >= 2) ? 10 : 0;  // source row for outputs w=2,3

    float mw[40], cw[4];
    #pragma unroll
    for (int w = 0; w < 4; ++w) {
        const int jw = (4 * phase + w) % 10;
        cw[w] = __ldg(&g_c3[jw]);
        #pragma unroll
        for (int k = 0; k < 10; ++k) mw[w * 10 + k] = __ldg(&g_M3[jw * 10 + k]);
    }

    float4* out4 = (float4*)out;

    // ================= APPLY (dynamic tile stealing, TMA pipeline) ===========
    long long i = 0;
    #pragma unroll 1
    while (true) {
        const int s = (int)(i % NSTAGE);
        const long long t = tidsm[s];        // uniform across block
        if (t < 0) break;
        const unsigned parity = (unsigned)((i / NSTAGE) & 1);
        mbar_wait(bar[s], parity);

        const float* st = &SH[STAGE0_F + s * STAGE_FLOATS];
        const long long tb = t * STAGE_PAIRS;

        #pragma unroll
        for (int it = 0; it < 5; ++it) {
            const int p = warp * 30 + it * 6 + lp;
            const long long gp = tb + p;
            if (active && gp < pairs) {
                const float2* rA = (const float2*)(st + p * 20 + offA);
                const float2* rB = (const float2*)(st + p * 20 + offB);
                float o0 = cw[0], o1 = cw[1], o2 = cw[2], o3 = cw[3];
                #pragma unroll
                for (int kk = 0; kk < 5; ++kk) {
                    const float2 a = rA[kk];
                    const float2 b = rB[kk];
                    o0 = fmaf(mw[2 * kk],          a.x, o0);
                    o0 = fmaf(mw[2 * kk + 1],      a.y, o0);
                    o1 = fmaf(mw[10 + 2 * kk],     a.x, o1);
                    o1 = fmaf(mw[10 + 2 * kk + 1], a.y, o1);
                    o2 = fmaf(mw[20 + 2 * kk],     b.x, o2);
                    o2 = fmaf(mw[20 + 2 * kk + 1], b.y, o2);
                    o3 = fmaf(mw[30 + 2 * kk],     b.x, o3);
                    o3 = fmaf(mw[30 + 2 * kk + 1], b.y, o3);
                }
                out4[gp * 5 + phase] = make_float4(o0, o1, o2, o3);
            }
        }

        __syncthreads();   // all warps done reading stage s
        if (tid == 0) {
            const long long nt = (long long)atomicAdd(&g_tile, 1u);
            if (nt < tiles) { tidsm[s] = nt; issue_tile(SH, bar[s], s, nt, pairs, x); }
            else            { tidsm[s] = -1; }
        }
        ++i;
    }

    // Odd-row tail (rows is even for this problem; kept for safety).
    if ((rows & 1LL) && cta == 0 && tid == 0) {
        const long long r = rows - 1;
        const float* xr = x + r * 10;
        float h[10];
        #pragma unroll
        for (int k = 0; k < 10; ++k) h[k] = xr[k];
        float* orow = out + r * 10;
        #pragma unroll
        for (int j = 0; j < 10; ++j) {
            float a = __ldg(&g_c3[j]);
            #pragma unroll
            for (int k = 0; k < 10; ++k) a += h[k] * __ldg(&g_M3[j * 10 + k]);
            orow[j] = a;
        }
    }

    // ================= RESET (replay-safe; last-finishing CTA) =================
    __syncthreads();
    __threadfence();
    if (tid == 0) {
        const unsigned old = atomicAdd(&g_done, 1u);
        if (old == gridDim.x - 1) {
            g_done = 0;
            g_ctr1 = 0;
            g_flag = 0;
            g_tile = 0;
        }
    }
}

extern "C" void kernel_launch(void* const* d_in, const int* in_sizes, int n_in,
                              void* d_out, int out_size) {
    // Identify inputs by element count: x=BATCH*10, Ws=1000*100, bs=1000*10.
    const float* x  = nullptr;
    const float* Ws = nullptr;
    const float* bs = nullptr;
    long long x_elems = 0;
    for (int i = 0; i < n_in; ++i) {
        if (in_sizes[i] == 1000 * 100) {
            Ws = (const float*)d_in[i];
        } else if (in_sizes[i] == 1000 * 10) {
            bs = (const float*)d_in[i];
        } else {
            x = (const float*)d_in[i];
            x_elems = in_sizes[i];
        }
    }
    const long long rows  = x_elems / 10;
    const long long pairs = rows >> 1;

    static int smem_set = 0;
    if (!smem_set) {
        cudaFuncSetAttribute(fused_kernel,
                             cudaFuncAttributeMaxDynamicSharedMemorySize, SMEM_BYTES);
        smem_set = 1;
    }
    // 296 CTAs = 2/SM (96.5KB smem each) -> whole grid is wave-1; dynamic tile
    // stealing balances the late-starting fold CTAs.
    fused_kernel<<<296, TPB, SMEM_BYTES>>>(Ws, bs, x, (float*)d_out, pairs, rows);
}